// round 11
// baseline (speedup 1.0000x reference)
#include <cuda_runtime.h>

// Exact L-inf nearest neighbor, scan-free bucket grid. 4 kernels:
//   zero_k   : zero per-cell counts + counters (fully parallel).
//   bucket_k : point -> bucket slot via atomicAdd rank; rank>=K -> global
//              overflow list (every query scans it in full; extra real
//              candidates are always sound).
//   fast_k   : 4 lanes/query; 3x3 halo cells cell-per-lane, u64 pack+min,
//              overflow sweep, wall-bound accept; failures stash (q, best).
//   slow_k   : ~one warp per failed query; scans BATCHED ANNULI (L..R=2L)
//              with flattened band/strip enumeration -> whole grid covered
//              in <=4 dependent iterations; wall-bound accept per batch.
// u64 pack (d_bits<<32 | idx<<19 | ovf<<18 | pos): min() IS the
// lexicographic (d, idx) compare -> exact jnp.argmin tie semantics.
// Wall soundness: out-of-range B points clamp into edge cells, so a wall
// touching the grid edge is dropped; every unscanned point lies strictly
// beyond a remaining wall (EPS-strict accept).

#define G      128
#define GH     (G + 2)                    // halo
#define NH     (GH * GH)                  // 16900
#define K      8
#define X0     (-4.5f)
#define EXT    9.0f
#define H      (EXT / (float)G)           // 0.0703125, binary exact
#define INVH   ((float)G / EXT)
#define EPS    1e-6f

__device__ int    g_cnt[NH];
__device__ float4 g_bkt[NH * K];          // (x, y, payload_bits, 0)
__device__ int    g_ovf_cnt;
__device__ float4 g_ovf[4096];
__device__ int    g_fail_cnt;
__device__ int    g_fail_q[32768];
__device__ unsigned long long g_fail_best[32768];

__device__ __forceinline__ int cell_coord(float v) {
    int c = __float2int_rd((v - X0) * INVH);
    return min(max(c, 0), G - 1);
}

// ---------------- build ----------------
__global__ void __launch_bounds__(256)
zero_k()
{
    int i = blockIdx.x * 256 + threadIdx.x;
    if (i < NH) g_cnt[i] = 0;
    if (i == 0) { g_ovf_cnt = 0; g_fail_cnt = 0; }
}

__global__ void __launch_bounds__(256)
bucket_k(const float* __restrict__ B, int N)
{
    int n = blockIdx.x * 256 + threadIdx.x;
    if (n >= N) return;
    float x = __ldg(&B[n]), y = __ldg(&B[N + n]);
    int h = (cell_coord(y) + 1) * GH + (cell_coord(x) + 1);
    int rank = atomicAdd(&g_cnt[h], 1);
    if (rank < K) {
        int pos = h * K + rank;
        unsigned pay = ((unsigned)n << 19) | (unsigned)pos;
        g_bkt[pos] = make_float4(x, y, __uint_as_float(pay), 0.0f);
    } else {
        int o = atomicAdd(&g_ovf_cnt, 1);
        unsigned pay = ((unsigned)n << 19) | (1u << 18) | (unsigned)o;
        g_ovf[o] = make_float4(x, y, __uint_as_float(pay), 0.0f);
    }
}

// ---------------- query helpers ----------------
__device__ __forceinline__ void eval_pt(float4 pt, float ax, float ay,
                                        unsigned long long& best)
{
    float d = fmaxf(fabsf(ax - pt.x), fabsf(ay - pt.y));
    unsigned long long c = (((unsigned long long)__float_as_uint(d)) << 32)
                         | (unsigned long long)__float_as_uint(pt.z);
    best = min(best, c);
}

__device__ __forceinline__ void scan_hcell(int h, float ax, float ay,
                                           unsigned long long& best)
{
    int cnt = min(__ldg(&g_cnt[h]), K);
    const float4* bp = &g_bkt[h * K];
    for (int j = 0; j < cnt; ++j) eval_pt(__ldg(&bp[j]), ax, ay, best);
}

__device__ __forceinline__ float2 fetch_win(unsigned long long best,
                                            float ax, float ay)
{
    unsigned pay = (unsigned)best;
    int pos = (int)(pay & 0x3FFFFu);
    float4 pt = (pay & (1u << 18)) ? __ldg(&g_ovf[pos]) : __ldg(&g_bkt[pos]);
    return make_float2(ax - pt.x, ay - pt.y);
}

// ---------------- fast kernel: 4 lanes/query ----------------
__global__ void __launch_bounds__(256, 8)
fast_k(const float* __restrict__ A, float* __restrict__ out, int Q)
{
    const int tid  = blockIdx.x * 256 + threadIdx.x;
    const int q    = tid >> 2;
    const int lane = tid & 3;
    if (q >= Q) return;

    const unsigned gmask = 0xFu << (threadIdx.x & 28);

    const float2 aq = __ldg(&((const float2*)A)[q]);
    const float ax = aq.x, ay = aq.y;
    const int cx = cell_coord(ax);
    const int cy = cell_coord(ay);
    const int hc = (cy + 1) * GH + (cx + 1);

    unsigned long long best = 0xFFFFFFFFFFFFFFFFull;

    {   // 3x3 cells, cell-per-lane (halo -> no boundary branches)
        int c1 = lane, c2 = lane + 4;
        int h1 = hc + (c1 / 3 - 1) * GH + (c1 % 3 - 1);
        int h2 = hc + (c2 / 3 - 1) * GH + (c2 % 3 - 1);
        scan_hcell(h1, ax, ay, best);
        scan_hcell(h2, ax, ay, best);
        if (lane == 0) scan_hcell(hc + GH + 1, ax, ay, best);
    }
    {   // full overflow sweep
        int oc = g_ovf_cnt;
        for (int o = lane; o < oc; o += 4)
            eval_pt(__ldg(&g_ovf[o]), ax, ay, best);
    }

    best = min(best, __shfl_xor_sync(gmask, best, 2));
    best = min(best, __shfl_xor_sync(gmask, best, 1));

    if (lane == 0) {
        float mb = __int_as_float(0x7f800000);
        if (cx - 1 > 0)     mb = fminf(mb, ax - (X0 + (float)(cx - 1) * H));
        if (cx + 1 < G - 1) mb = fminf(mb, (X0 + (float)(cx + 2) * H) - ax);
        if (cy - 1 > 0)     mb = fminf(mb, ay - (X0 + (float)(cy - 1) * H));
        if (cy + 1 < G - 1) mb = fminf(mb, (X0 + (float)(cy + 2) * H) - ay);

        float bd = __uint_as_float((unsigned)(best >> 32));
        if (bd <= mb - EPS) {
            ((float2*)out)[q] = fetch_win(best, ax, ay);
        } else {
            int slot = atomicAdd(&g_fail_cnt, 1);
            g_fail_q[slot]    = q;
            g_fail_best[slot] = best;
        }
    }
}

// ---------------- slow kernel: one warp per failed query ----------------
// Scans annuli [L..R] in one shot. Flattened enumeration:
//   bands : rows |dj| in [L..R], full width W = 2R+1
//   strips: rows |dj| <  L, left/right columns, S = R-L+1 each side
__global__ void __launch_bounds__(256)
slow_k(const float* __restrict__ A, float* __restrict__ out, int nwarps_total)
{
    const int wglob = blockIdx.x * 8 + (threadIdx.x >> 5);
    const int lane  = threadIdx.x & 31;
    const int cnt   = g_fail_cnt;

    for (int f = wglob; f < cnt; f += nwarps_total) {
        const int q = g_fail_q[f];
        const float2 aq = __ldg(&((const float2*)A)[q]);
        const float ax = aq.x, ay = aq.y;
        const int cx = cell_coord(ax);
        const int cy = cell_coord(ay);

        unsigned long long best = (lane == 0) ? g_fail_best[f]
                                              : 0xFFFFFFFFFFFFFFFFull;
        best = __shfl_sync(0xffffffffu, best, 0);

        int L = 2;                               // rings 0,1 + ovf done by fast
        for (;;) {
            const int R = 2 * L;
            const int S = R - L + 1;
            const int W = 2 * R + 1;
            const int nBand  = 2 * S * W;        // top+bottom full rows
            const int T      = nBand + (2 * L - 1) * 2 * S;

            for (int tc = lane; tc < T; tc += 32) {
                int i, j;
                if (tc < nBand) {
                    int row = tc / W, col = tc - row * W;
                    j = (row < S) ? (cy - R + row) : (cy + L + (row - S));
                    i = cx - R + col;
                } else {
                    int t2 = tc - nBand;
                    int row = t2 / (2 * S), k = t2 - row * (2 * S);
                    j = cy - L + 1 + row;
                    i = (k < S) ? (cx - R + k) : (cx + L + (k - S));
                }
                if ((unsigned)i < G && (unsigned)j < G)
                    scan_hcell((j + 1) * GH + (i + 1), ax, ay, best);
            }
            #pragma unroll
            for (int m = 16; m >= 1; m >>= 1)
                best = min(best, __shfl_xor_sync(0xffffffffu, best, m));

            if (cx - R <= 0 && cx + R >= G - 1 &&
                cy - R <= 0 && cy + R >= G - 1) break;   // grid exhausted
            float mb = __int_as_float(0x7f800000);
            if (cx - R > 0)     mb = fminf(mb, ax - (X0 + (float)(cx - R) * H));
            if (cx + R < G - 1) mb = fminf(mb, (X0 + (float)(cx + R + 1) * H) - ax);
            if (cy - R > 0)     mb = fminf(mb, ay - (X0 + (float)(cy - R) * H));
            if (cy + R < G - 1) mb = fminf(mb, (X0 + (float)(cy + R + 1) * H) - ay);
            float bd = __uint_as_float((unsigned)(best >> 32));
            if (bd <= mb - EPS) break;

            L = R + 1;                            // next annulus
        }

        if (lane == 0)
            ((float2*)out)[q] = fetch_win(best, ax, ay);
    }
}

extern "C" void kernel_launch(void* const* d_in, const int* in_sizes, int n_in,
                              void* d_out, int out_size)
{
    const float* A = (const float*)d_in[0];   // [Q, 2]
    const float* B = (const float*)d_in[1];   // [2, N]
    float*     out = (float*)d_out;           // [Q, 2]

    const int Q = in_sizes[0] / 2;
    const int N = in_sizes[1] / 2;

    zero_k  <<<(NH + 255) / 256, 256>>>();
    bucket_k<<<(N + 255) / 256, 256>>>(B, N);

    fast_k<<<(Q * 4 + 255) / 256, 256>>>(A, out, Q);

    const int slow_blocks = 512;              // 4096 warps
    slow_k<<<slow_blocks, 256>>>(A, out, slow_blocks * 8);
}

// round 12
// speedup vs baseline: 1.8734x; 1.8734x over previous
#include <cuda_runtime.h>

// Exact L-inf nearest neighbor. 4 kernels:
//   zero_k   : zero per-cell counts + counters (fully parallel).
//   bucket_k : point -> fixed-K bucket via atomicAdd rank; overflow points
//              go to a global list every query also scans (extra real
//              candidates never hurt correctness).
//   fast_k   : 4 lanes/query; 3x3 halo cells cell-per-lane, u64 pack+min,
//              overflow sweep, geometric wall-bound accept (margin >= H);
//              failures are compacted to a list.
//   slow_k   : one warp per failed query; UNIFORM BRUTE FORCE over all of B
//              (128 evals/lane, unrolled, coalesced SoA loads). Pack
//              d_bits<<32|n -> u64 min IS jnp.argmin first-index semantics,
//              unconditionally exact. No geometry, no bounds, fixed cost.
// Wall soundness (fast path): out-of-range B points clamp into edge cells,
// so a wall touching the grid edge is dropped; every unscanned point lies
// strictly beyond a remaining wall (EPS-strict accept).

#define G      128
#define GH     (G + 2)                    // halo
#define NH     (GH * GH)                  // 16900
#define K      8
#define X0     (-4.5f)
#define EXT    9.0f
#define H      (EXT / (float)G)           // 0.0703125, binary exact
#define INVH   ((float)G / EXT)
#define EPS    1e-6f

__device__ int    g_cnt[NH];
__device__ float4 g_bkt[NH * K];          // (x, y, payload_bits, 0)
__device__ int    g_ovf_cnt;
__device__ float4 g_ovf[4096];
__device__ int    g_fail_cnt;
__device__ int    g_fail_q[32768];

__device__ __forceinline__ int cell_coord(float v) {
    int c = __float2int_rd((v - X0) * INVH);
    return min(max(c, 0), G - 1);
}

// ---------------- build ----------------
__global__ void __launch_bounds__(256)
zero_k()
{
    int i = blockIdx.x * 256 + threadIdx.x;
    if (i < NH) g_cnt[i] = 0;
    if (i == 0) { g_ovf_cnt = 0; g_fail_cnt = 0; }
}

__global__ void __launch_bounds__(256)
bucket_k(const float* __restrict__ B, int N)
{
    int n = blockIdx.x * 256 + threadIdx.x;
    if (n >= N) return;
    float x = __ldg(&B[n]), y = __ldg(&B[N + n]);
    int h = (cell_coord(y) + 1) * GH + (cell_coord(x) + 1);
    int rank = atomicAdd(&g_cnt[h], 1);
    if (rank < K) {
        int pos = h * K + rank;
        unsigned pay = ((unsigned)n << 19) | (unsigned)pos;
        g_bkt[pos] = make_float4(x, y, __uint_as_float(pay), 0.0f);
    } else {
        int o = atomicAdd(&g_ovf_cnt, 1);
        unsigned pay = ((unsigned)n << 19) | (1u << 18) | (unsigned)o;
        g_ovf[o] = make_float4(x, y, __uint_as_float(pay), 0.0f);
    }
}

// ---------------- fast-path helpers ----------------
__device__ __forceinline__ void eval_pt(float4 pt, float ax, float ay,
                                        unsigned long long& best)
{
    float d = fmaxf(fabsf(ax - pt.x), fabsf(ay - pt.y));
    unsigned long long c = (((unsigned long long)__float_as_uint(d)) << 32)
                         | (unsigned long long)__float_as_uint(pt.z);
    best = min(best, c);
}

__device__ __forceinline__ void scan_hcell(int h, float ax, float ay,
                                           unsigned long long& best)
{
    int cnt = min(__ldg(&g_cnt[h]), K);
    const float4* bp = &g_bkt[h * K];
    for (int j = 0; j < cnt; ++j) eval_pt(__ldg(&bp[j]), ax, ay, best);
}

// ---------------- fast kernel: 4 lanes/query ----------------
__global__ void __launch_bounds__(256, 8)
fast_k(const float* __restrict__ A, float* __restrict__ out, int Q)
{
    const int tid  = blockIdx.x * 256 + threadIdx.x;
    const int q    = tid >> 2;
    const int lane = tid & 3;
    if (q >= Q) return;

    const unsigned gmask = 0xFu << (threadIdx.x & 28);

    const float2 aq = __ldg(&((const float2*)A)[q]);
    const float ax = aq.x, ay = aq.y;
    const int cx = cell_coord(ax);
    const int cy = cell_coord(ay);
    const int hc = (cy + 1) * GH + (cx + 1);

    unsigned long long best = 0xFFFFFFFFFFFFFFFFull;

    {   // 3x3 cells, cell-per-lane (halo -> no boundary branches)
        int c1 = lane, c2 = lane + 4;
        int h1 = hc + (c1 / 3 - 1) * GH + (c1 % 3 - 1);
        int h2 = hc + (c2 / 3 - 1) * GH + (c2 % 3 - 1);
        scan_hcell(h1, ax, ay, best);
        scan_hcell(h2, ax, ay, best);
        if (lane == 0) scan_hcell(hc + GH + 1, ax, ay, best);
    }
    {   // full overflow sweep (expected tiny)
        int oc = g_ovf_cnt;
        for (int o = lane; o < oc; o += 4)
            eval_pt(__ldg(&g_ovf[o]), ax, ay, best);
    }

    best = min(best, __shfl_xor_sync(gmask, best, 2));
    best = min(best, __shfl_xor_sync(gmask, best, 1));

    if (lane == 0) {
        float mb = __int_as_float(0x7f800000);
        if (cx - 1 > 0)     mb = fminf(mb, ax - (X0 + (float)(cx - 1) * H));
        if (cx + 1 < G - 1) mb = fminf(mb, (X0 + (float)(cx + 2) * H) - ax);
        if (cy - 1 > 0)     mb = fminf(mb, ay - (X0 + (float)(cy - 1) * H));
        if (cy + 1 < G - 1) mb = fminf(mb, (X0 + (float)(cy + 2) * H) - ay);

        float bd = __uint_as_float((unsigned)(best >> 32));
        if (bd <= mb - EPS) {
            unsigned pay = (unsigned)best;
            int pos = (int)(pay & 0x3FFFFu);
            float4 pt = (pay & (1u << 18)) ? __ldg(&g_ovf[pos])
                                           : __ldg(&g_bkt[pos]);
            ((float2*)out)[q] = make_float2(ax - pt.x, ay - pt.y);
        } else {
            int slot = atomicAdd(&g_fail_cnt, 1);
            g_fail_q[slot] = q;
        }
    }
}

// ---------------- slow kernel: warp-per-query brute force ----------------
__global__ void __launch_bounds__(256)
slow_k(const float* __restrict__ A, const float* __restrict__ B,
       float* __restrict__ out, int N, int Q, int nwarps_total)
{
    const int wglob = blockIdx.x * 8 + (threadIdx.x >> 5);
    const int lane  = threadIdx.x & 31;
    const int cnt   = g_fail_cnt;

    const float* __restrict__ Bx = B;
    const float* __restrict__ By = B + N;

    for (int f = wglob; f < cnt; f += nwarps_total) {
        const int q = g_fail_q[f];
        const float2 aq = __ldg(&((const float2*)A)[q]);
        const float ax = aq.x, ay = aq.y;

        unsigned long long best = 0xFFFFFFFFFFFFFFFFull;

        int n = lane;
        // unrolled x4: independent coalesced loads, deep MLP
        for (; n + 96 < N; n += 128) {
            float x0 = __ldg(&Bx[n]),      y0 = __ldg(&By[n]);
            float x1 = __ldg(&Bx[n + 32]), y1 = __ldg(&By[n + 32]);
            float x2 = __ldg(&Bx[n + 64]), y2 = __ldg(&By[n + 64]);
            float x3 = __ldg(&Bx[n + 96]), y3 = __ldg(&By[n + 96]);
            float d0 = fmaxf(fabsf(ax - x0), fabsf(ay - y0));
            float d1 = fmaxf(fabsf(ax - x1), fabsf(ay - y1));
            float d2 = fmaxf(fabsf(ax - x2), fabsf(ay - y2));
            float d3 = fmaxf(fabsf(ax - x3), fabsf(ay - y3));
            best = min(best, (((unsigned long long)__float_as_uint(d0)) << 32) | (unsigned)(n));
            best = min(best, (((unsigned long long)__float_as_uint(d1)) << 32) | (unsigned)(n + 32));
            best = min(best, (((unsigned long long)__float_as_uint(d2)) << 32) | (unsigned)(n + 64));
            best = min(best, (((unsigned long long)__float_as_uint(d3)) << 32) | (unsigned)(n + 96));
        }
        for (; n < N; n += 32) {
            float x = __ldg(&Bx[n]), y = __ldg(&By[n]);
            float d = fmaxf(fabsf(ax - x), fabsf(ay - y));
            best = min(best, (((unsigned long long)__float_as_uint(d)) << 32) | (unsigned)n);
        }

        #pragma unroll
        for (int m = 16; m >= 1; m >>= 1)
            best = min(best, __shfl_xor_sync(0xffffffffu, best, m));

        if (lane == 0) {
            int nb = (int)(best & 0xFFFFFFFFu);
            ((float2*)out)[q] = make_float2(ax - __ldg(&Bx[nb]),
                                            ay - __ldg(&By[nb]));
        }
    }
}

extern "C" void kernel_launch(void* const* d_in, const int* in_sizes, int n_in,
                              void* d_out, int out_size)
{
    const float* A = (const float*)d_in[0];   // [Q, 2]
    const float* B = (const float*)d_in[1];   // [2, N]
    float*     out = (float*)d_out;           // [Q, 2]

    const int Q = in_sizes[0] / 2;
    const int N = in_sizes[1] / 2;

    zero_k  <<<(NH + 255) / 256, 256>>>();
    bucket_k<<<(N + 255) / 256, 256>>>(B, N);

    fast_k<<<(Q * 4 + 255) / 256, 256>>>(A, out, Q);

    const int slow_blocks = 384;              // 3072 warps, grid-stride
    slow_k<<<slow_blocks, 256>>>(A, B, out, N, Q, slow_blocks * 8);
}

// round 13
// speedup vs baseline: 2.2753x; 1.2145x over previous
#include <cuda_runtime.h>

// Exact L-inf nearest neighbor. 4 kernels:
//   zero_k   : zero per-cell counts + counters (fully parallel).
//   bucket_k : point -> fixed-K bucket via atomicAdd rank; overflow points
//              go to a global list every query also scans (extra real
//              candidates never hurt correctness).
//   fast_k   : 4 lanes/query. Pass 1: 3x3 halo cells cell-per-lane + ovf
//              sweep + wall-bound accept. Pass 2 (only if bound fails):
//              ring 2 (16 cells, 4/lane) + 5x5 wall bound. Residual
//              failures compacted to a list.
//   slow_k   : ONE BLOCK per failed query; brute force over all of B with
//              coalesced float4 SoA loads (16 cands/thread), two-stage
//              u64-min reduce. Pack d_bits<<32|n -> u64 min IS jnp.argmin
//              first-index semantics; unconditionally exact.
// Wall soundness (fast path): out-of-range B points clamp into edge cells,
// so a wall touching the grid edge is dropped; every unscanned point lies
// strictly beyond a remaining wall (EPS-strict accept).

#define G      128
#define HALO   2
#define GH     (G + 2 * HALO)             // 132
#define NH     (GH * GH)                  // 17424
#define K      8
#define X0     (-4.5f)
#define EXT    9.0f
#define H      (EXT / (float)G)           // 0.0703125, binary exact
#define INVH   ((float)G / EXT)
#define EPS    1e-6f

__device__ int    g_cnt[NH];
__device__ float4 g_bkt[NH * K];          // (x, y, payload_bits, 0)
__device__ int    g_ovf_cnt;
__device__ float4 g_ovf[4096];
__device__ int    g_fail_cnt;
__device__ int    g_fail_q[32768];

__device__ __forceinline__ int cell_coord(float v) {
    int c = __float2int_rd((v - X0) * INVH);
    return min(max(c, 0), G - 1);
}

// ---------------- build ----------------
__global__ void __launch_bounds__(256)
zero_k()
{
    int i = blockIdx.x * 256 + threadIdx.x;
    if (i < NH) g_cnt[i] = 0;
    if (i == 0) { g_ovf_cnt = 0; g_fail_cnt = 0; }
}

__global__ void __launch_bounds__(256)
bucket_k(const float* __restrict__ B, int N)
{
    int n = blockIdx.x * 256 + threadIdx.x;
    if (n >= N) return;
    float x = __ldg(&B[n]), y = __ldg(&B[N + n]);
    int h = (cell_coord(y) + HALO) * GH + (cell_coord(x) + HALO);
    int rank = atomicAdd(&g_cnt[h], 1);
    if (rank < K) {
        int pos = h * K + rank;
        unsigned pay = ((unsigned)n << 19) | (unsigned)pos;
        g_bkt[pos] = make_float4(x, y, __uint_as_float(pay), 0.0f);
    } else {
        int o = atomicAdd(&g_ovf_cnt, 1);
        unsigned pay = ((unsigned)n << 19) | (1u << 18) | (unsigned)o;
        g_ovf[o] = make_float4(x, y, __uint_as_float(pay), 0.0f);
    }
}

// ---------------- fast-path helpers ----------------
__device__ __forceinline__ void eval_pt(float4 pt, float ax, float ay,
                                        unsigned long long& best)
{
    float d = fmaxf(fabsf(ax - pt.x), fabsf(ay - pt.y));
    unsigned long long c = (((unsigned long long)__float_as_uint(d)) << 32)
                         | (unsigned long long)__float_as_uint(pt.z);
    best = min(best, c);
}

__device__ __forceinline__ void scan_hcell(int h, float ax, float ay,
                                           unsigned long long& best)
{
    int cnt = min(__ldg(&g_cnt[h]), K);
    const float4* bp = &g_bkt[h * K];
    for (int j = 0; j < cnt; ++j) eval_pt(__ldg(&bp[j]), ax, ay, best);
}

// wall bound of covered rect cells [cx-r..cx+r] x [cy-r..cy+r] (edge walls dropped)
__device__ __forceinline__ float wall_bound(float ax, float ay,
                                            int cx, int cy, int r)
{
    float mb = __int_as_float(0x7f800000);
    if (cx - r > 0)     mb = fminf(mb, ax - (X0 + (float)(cx - r) * H));
    if (cx + r < G - 1) mb = fminf(mb, (X0 + (float)(cx + r + 1) * H) - ax);
    if (cy - r > 0)     mb = fminf(mb, ay - (X0 + (float)(cy - r) * H));
    if (cy + r < G - 1) mb = fminf(mb, (X0 + (float)(cy + r + 1) * H) - ay);
    return mb;
}

// ---------------- fast kernel: 4 lanes/query ----------------
__global__ void __launch_bounds__(256, 8)
fast_k(const float* __restrict__ A, float* __restrict__ out, int Q)
{
    const int tid  = blockIdx.x * 256 + threadIdx.x;
    const int q    = tid >> 2;
    const int lane = tid & 3;
    if (q >= Q) return;

    const unsigned gmask = 0xFu << (threadIdx.x & 28);

    const float2 aq = __ldg(&((const float2*)A)[q]);
    const float ax = aq.x, ay = aq.y;
    const int cx = cell_coord(ax);
    const int cy = cell_coord(ay);
    const int hc = (cy + HALO) * GH + (cx + HALO);

    unsigned long long best = 0xFFFFFFFFFFFFFFFFull;

    {   // 3x3 cells, cell-per-lane (halo -> no boundary branches)
        int c1 = lane, c2 = lane + 4;
        int h1 = hc + (c1 / 3 - 1) * GH + (c1 % 3 - 1);
        int h2 = hc + (c2 / 3 - 1) * GH + (c2 % 3 - 1);
        scan_hcell(h1, ax, ay, best);
        scan_hcell(h2, ax, ay, best);
        if (lane == 0) scan_hcell(hc + GH + 1, ax, ay, best);
    }
    {   // full overflow sweep (expected tiny)
        int oc = g_ovf_cnt;
        for (int o = lane; o < oc; o += 4)
            eval_pt(__ldg(&g_ovf[o]), ax, ay, best);
    }

    best = min(best, __shfl_xor_sync(gmask, best, 2));
    best = min(best, __shfl_xor_sync(gmask, best, 1));

    float mb = wall_bound(ax, ay, cx, cy, 1);
    bool ok = __uint_as_float((unsigned)(best >> 32)) <= mb - EPS;

    if (!ok) {
        // second chance: ring 2 (16 cells, 4 per lane), then 5x5 bound
        #pragma unroll
        for (int k = 0; k < 4; ++k) {
            int tc = lane * 4 + k;
            int di, dj;
            if (tc < 5)       { di = tc - 2;        dj = -2; }
            else if (tc < 10) { di = tc - 7;        dj =  2; }
            else { int t2 = tc - 10; dj = (t2 >> 1) - 1; di = (t2 & 1) ? 2 : -2; }
            scan_hcell(hc + dj * GH + di, ax, ay, best);
        }
        best = min(best, __shfl_xor_sync(gmask, best, 2));
        best = min(best, __shfl_xor_sync(gmask, best, 1));
        mb = wall_bound(ax, ay, cx, cy, 2);
        ok = __uint_as_float((unsigned)(best >> 32)) <= mb - EPS;
    }

    if (lane == 0) {
        if (ok) {
            unsigned pay = (unsigned)best;
            int pos = (int)(pay & 0x3FFFFu);
            float4 pt = (pay & (1u << 18)) ? __ldg(&g_ovf[pos])
                                           : __ldg(&g_bkt[pos]);
            ((float2*)out)[q] = make_float2(ax - pt.x, ay - pt.y);
        } else {
            int slot = atomicAdd(&g_fail_cnt, 1);
            g_fail_q[slot] = q;
        }
    }
}

// ---------------- slow kernel: ONE BLOCK per failed query ----------------
__global__ void __launch_bounds__(256)
slow_k(const float* __restrict__ A, const float* __restrict__ B,
       float* __restrict__ out, int N)
{
    __shared__ unsigned long long s_best[8];

    const int cnt = g_fail_cnt;
    const int t    = threadIdx.x;
    const int lane = t & 31;
    const int wid  = t >> 5;

    const bool vec_ok = ((N & 3) == 0);
    const int  Nvec   = vec_ok ? (N & ~1023) : 0;   // multiple of 1024
    const float4* __restrict__ Bx4 = (const float4*)B;
    const float4* __restrict__ By4 = (const float4*)(B + N);

    for (int f = blockIdx.x; f < cnt; f += gridDim.x) {
        __syncthreads();                             // s_best reuse guard
        const int q = g_fail_q[f];
        const float2 aq = __ldg(&((const float2*)A)[q]);
        const float ax = aq.x, ay = aq.y;

        unsigned long long best = 0xFFFFFFFFFFFFFFFFull;

        // vector part: thread t, step k -> float4 index t + 256*k (coalesced)
        for (int k = 0; k * 1024 < Nvec; ++k) {
            int i4 = t + (k << 8);
            float4 xs = __ldg(&Bx4[i4]);
            float4 ys = __ldg(&By4[i4]);
            int n0 = i4 << 2;
            float d0 = fmaxf(fabsf(ax - xs.x), fabsf(ay - ys.x));
            float d1 = fmaxf(fabsf(ax - xs.y), fabsf(ay - ys.y));
            float d2 = fmaxf(fabsf(ax - xs.z), fabsf(ay - ys.z));
            float d3 = fmaxf(fabsf(ax - xs.w), fabsf(ay - ys.w));
            best = min(best, (((unsigned long long)__float_as_uint(d0)) << 32) | (unsigned)(n0));
            best = min(best, (((unsigned long long)__float_as_uint(d1)) << 32) | (unsigned)(n0 + 1));
            best = min(best, (((unsigned long long)__float_as_uint(d2)) << 32) | (unsigned)(n0 + 2));
            best = min(best, (((unsigned long long)__float_as_uint(d3)) << 32) | (unsigned)(n0 + 3));
        }
        // scalar remainder
        for (int n = Nvec + t; n < N; n += 256) {
            float d = fmaxf(fabsf(ax - __ldg(&B[n])), fabsf(ay - __ldg(&B[N + n])));
            best = min(best, (((unsigned long long)__float_as_uint(d)) << 32) | (unsigned)n);
        }

        #pragma unroll
        for (int m = 16; m >= 1; m >>= 1)
            best = min(best, __shfl_xor_sync(0xffffffffu, best, m));
        if (lane == 0) s_best[wid] = best;
        __syncthreads();

        if (wid == 0) {
            best = (lane < 8) ? s_best[lane] : 0xFFFFFFFFFFFFFFFFull;
            #pragma unroll
            for (int m = 4; m >= 1; m >>= 1)
                best = min(best, __shfl_xor_sync(0xffffffffu, best, m));
            if (lane == 0) {
                int nb = (int)(best & 0xFFFFFFFFu);
                ((float2*)out)[q] = make_float2(ax - __ldg(&B[nb]),
                                                ay - __ldg(&B[N + nb]));
            }
        }
    }
}

extern "C" void kernel_launch(void* const* d_in, const int* in_sizes, int n_in,
                              void* d_out, int out_size)
{
    const float* A = (const float*)d_in[0];   // [Q, 2]
    const float* B = (const float*)d_in[1];   // [2, N]
    float*     out = (float*)d_out;           // [Q, 2]

    const int Q = in_sizes[0] / 2;
    const int N = in_sizes[1] / 2;

    zero_k  <<<(NH + 255) / 256, 256>>>();
    bucket_k<<<(N + 255) / 256, 256>>>(B, N);

    fast_k<<<(Q * 4 + 255) / 256, 256>>>(A, out, Q);

    slow_k<<<1024, 256>>>(A, B, out, N);      // one block per failed query
}